// round 2
// baseline (speedup 1.0000x reference)
#include <cuda_runtime.h>
#include <cuda_bf16.h>
#include <math.h>

#define Hx   24
#define Dx   128
#define NHx  4
#define DHx  32
#define FFx  512
#define RS32 0.17677669529663687f  /* 1/sqrt(32) */

// ---------------------------------------------------------------------------
// Precomputed batch-independent tables (device globals; recomputed per launch)
// ---------------------------------------------------------------------------
__device__ float g_E [2][3][Hx][Dx];      // Qe/Ke/Ve = fe @ W{q,k,v}^T
__device__ float g_G [2][NHx][Hx][Hx];    // (Qe_i . Ke_j)/sqrt(DH)
__device__ float g_Mk[2][NHx][Hx][Hx];    // mask bias + qb.kb/sqrt(DH), -1e30 invalid
__device__ float g_gq[2][NHx][Hx];
__device__ float g_gk[2][NHx][Hx];
__device__ float g_P [2][NHx*Hx][Dx];     // out_w (head slice) @ Ve
__device__ float g_Pc[2][Dx];             // out_b + out_w @ vb
__device__ float g_gw[2][Dx];             // ln2_g * op_w * alpha
__device__ float g_sc[2][2];              // [br][0]=sum(gw), [1]=alpha*(sum(ln2_b*op_w)+op_b)

// ---------------------------------------------------------------------------
// Precompute 1: Qe/Ke/Ve  (grid 6 = 2 branches x {q,k,v})
// ---------------------------------------------------------------------------
__global__ void pre_qkv(const float* __restrict__ fe,
                        const float* __restrict__ inwp,
                        const float* __restrict__ inwf) {
    int br = blockIdx.x / 3, which = blockIdx.x % 3;
    const float* W = (br ? inwf : inwp) + which * Dx * Dx;
    __shared__ float fes[Hx * Dx];
    for (int idx = threadIdx.x; idx < Hx * Dx; idx += blockDim.x) fes[idx] = fe[idx];
    __syncthreads();
    for (int idx = threadIdx.x; idx < Hx * Dx; idx += blockDim.x) {
        int i = idx >> 7, c = idx & 127;
        float s = 0.f;
        #pragma unroll 8
        for (int d = 0; d < Dx; d++) s += fes[i * Dx + d] * W[c * Dx + d];
        g_E[br][which][i][c] = s;
    }
}

// ---------------------------------------------------------------------------
// Precompute 2: G, Mk, gq, gk, P, Pc, gw, scalars  (grid 2 = branches)
// ---------------------------------------------------------------------------
__global__ void pre_misc(const float* __restrict__ inbp, const float* __restrict__ inbf,
                         const float* __restrict__ outwp, const float* __restrict__ outbp,
                         const float* __restrict__ outwf, const float* __restrict__ outbf,
                         const float* __restrict__ ln2g, const float* __restrict__ ln2b,
                         const float* __restrict__ oppw, const float* __restrict__ oppb,
                         const float* __restrict__ opfw, const float* __restrict__ opfb,
                         const float* __restrict__ alog,
                         const float* __restrict__ biasp, const float* __restrict__ biasf) {
    int br = blockIdx.x;
    const float* inb  = br ? inbf  : inbp;
    const float* outw = br ? outwf : outwp;
    const float* outb = br ? outbf : outbp;
    const float* opw  = br ? opfw  : oppw;
    const float* opb  = br ? opfb  : oppb;
    const float* bias = br ? biasf : biasp;
    const float* qb = inb, *kb = inb + Dx, *vb = inb + 2 * Dx;
    __shared__ float g0s[NHx];
    int tid = threadIdx.x;
    if (tid < NHx) {
        float s = 0.f;
        for (int d = 0; d < DHx; d++) s += qb[tid * DHx + d] * kb[tid * DHx + d];
        g0s[tid] = s * RS32;
    }
    __syncthreads();
    for (int idx = tid; idx < NHx * Hx; idx += blockDim.x) {
        int n = idx / Hx, i = idx % Hx;
        float s1 = 0.f, s2 = 0.f;
        for (int d = 0; d < DHx; d++) {
            s1 += g_E[br][0][i][n * DHx + d] * kb[n * DHx + d];
            s2 += g_E[br][1][i][n * DHx + d] * qb[n * DHx + d];
        }
        g_gq[br][n][i] = s1 * RS32;
        g_gk[br][n][i] = s2 * RS32;
    }
    for (int idx = tid; idx < NHx * Hx * Hx; idx += blockDim.x) {
        int n = idx / (Hx * Hx), i = (idx / Hx) % Hx, j = idx % Hx;
        float s = 0.f;
        for (int d = 0; d < DHx; d++)
            s += g_E[br][0][i][n * DHx + d] * g_E[br][1][j][n * DHx + d];
        g_G[br][n][i][j] = s * RS32;
        bool valid = (br == 0) ? (j <= i) : (j >= i);
        g_Mk[br][n][i][j] = valid ? bias[j - i + Hx - 1] + g0s[n] : -1e30f;
    }
    for (int idx = tid; idx < NHx * Hx * Dx; idx += blockDim.x) {
        int k = idx >> 7, c = idx & 127;
        int n = k / Hx, j = k % Hx;
        float s = 0.f;
        for (int d = 0; d < DHx; d++)
            s += outw[c * Dx + n * DHx + d] * g_E[br][2][j][n * DHx + d];
        g_P[br][k][c] = s;
    }
    float e0 = expf(alog[0]), e1 = expf(alog[1]);
    float alpha = (br == 0 ? e0 : e1) / (e0 + e1);
    for (int idx = tid; idx < Dx; idx += blockDim.x) {
        float s = outb[idx];
        for (int m = 0; m < Dx; m++) s += outw[idx * Dx + m] * vb[m];
        g_Pc[br][idx] = s;
        g_gw[br][idx] = ln2g[idx] * opw[idx] * alpha;
    }
    __syncthreads();
    __threadfence();
    if (tid == 0) {
        float sgw = 0.f, cst = 0.f;
        for (int c = 0; c < Dx; c++) { sgw += g_gw[br][c]; cst += ln2b[c] * opw[c]; }
        g_sc[br][0] = sgw;
        g_sc[br][1] = alpha * (cst + opb[0]);
    }
}

// ---------------------------------------------------------------------------
// Fused main kernel: 4 batch elems (96 rows) per 256-thread block, both branches
// ---------------------------------------------------------------------------
#define TSTR  133   // tsm / fesm row stride
#define PSTR  132   // Psm row stride (float4-aligned)
#define WSTR  97    // attention-weight row stride
#define W1STR 68    // W1^T [c][f] row stride (float4-aligned)
#define W2STR 132   // W2  [f][c] row stride (float4-aligned)
#define HSTR  69    // h row stride
#define SMEM_FLOATS 40376

__global__ __launch_bounds__(256)
void fused_main(const float* __restrict__ z, const float* __restrict__ fe,
                const float* __restrict__ ln1g, const float* __restrict__ ln1b,
                const float* __restrict__ w1, const float* __restrict__ b1,
                const float* __restrict__ w2, const float* __restrict__ b2,
                float* __restrict__ out) {
    extern __shared__ float sm[];
    float* zsm   = sm;            // 96
    float* outsm = sm + 96;       // 96
    float* c1g   = sm + 192;      // 128
    float* c1b   = sm + 320;      // 128
    float* cb2   = sm + 448;      // 128
    float* fesm  = sm + 576;      // 24*133 = 3192
    float* tsm   = sm + 3768;     // 96*133 = 12768
    float* X     = sm + 16536;    // union region: 23840 floats
    float* Psm = X;               // 96*132
    float* Wsm = X + 12672;       // 96*97
    float* W1T = X;               // 128*68
    float* W2s = X + 8704;        // 64*132
    float* hs  = X + 17152;       // 96*69
    float* b1c = X + 23776;       // 64

    int tid = threadIdx.x;
    int tx = tid & 15, ty = tid >> 4;
    int blk = blockIdx.x;
    int r0 = ty * 6, c0 = tx * 8;

    if (tid < 96) { zsm[tid] = z[blk * 96 + tid]; outsm[tid] = 0.f; }
    if (tid < 128) { c1g[tid] = ln1g[tid]; c1b[tid] = ln1b[tid]; cb2[tid] = b2[tid]; }
    for (int idx = tid; idx < Hx * Dx; idx += 256)
        fesm[(idx >> 7) * TSTR + (idx & 127)] = fe[idx];
    __syncthreads();

    for (int br = 0; br < 2; br++) {
        // ---- stage P ----
        const float* gP = &g_P[br][0][0];
        for (int idx = tid; idx < 96 * 128; idx += 256)
            Psm[(idx >> 7) * PSTR + (idx & 127)] = gP[idx];
        // ---- scores + softmax + weight fold (384 rows of 24) ----
        for (int rs = tid; rs < 384; rs += 256) {
            int bb = rs / 96, rem = rs % 96, n = rem / 24, i = rem % 24;
            float zi = zsm[bb * 24 + i];
            const float* Gp  = &g_G[br][n][i][0];
            const float* Mp  = &g_Mk[br][n][i][0];
            const float* gkp = &g_gk[br][n][0];
            float gq = g_gq[br][n][i];
            float s[24]; float mx = -1e30f;
            #pragma unroll
            for (int j = 0; j < 24; j++) {
                float zj = zsm[bb * 24 + j];
                float v = zi * zj * Gp[j] + zi * gq + zj * gkp[j] + Mp[j];
                s[j] = v; mx = fmaxf(mx, v);
            }
            float sum = 0.f;
            #pragma unroll
            for (int j = 0; j < 24; j++) {
                s[j] = __expf(fmaxf(s[j] - mx, -80.f));
                sum += s[j];
            }
            float inv = 1.f / sum;
            float* wrow = &Wsm[(bb * 24 + i) * WSTR + n * 24];
            #pragma unroll
            for (int j = 0; j < 24; j++) wrow[j] = s[j] * inv * zsm[bb * 24 + j];
        }
        __syncthreads();

        // ---- attention GEMM: o[96][128] = W[96][96] @ P[96][128] ----
        float acc[6][8];
        #pragma unroll
        for (int u = 0; u < 6; u++)
            #pragma unroll
            for (int v = 0; v < 8; v++) acc[u][v] = 0.f;
        for (int k = 0; k < 96; k++) {
            float wv[6];
            #pragma unroll
            for (int u = 0; u < 6; u++) wv[u] = Wsm[(r0 + u) * WSTR + k];
            float4 p0 = *(const float4*)&Psm[k * PSTR + c0];
            float4 p1 = *(const float4*)&Psm[k * PSTR + c0 + 4];
            #pragma unroll
            for (int u = 0; u < 6; u++) {
                acc[u][0] += wv[u] * p0.x; acc[u][1] += wv[u] * p0.y;
                acc[u][2] += wv[u] * p0.z; acc[u][3] += wv[u] * p0.w;
                acc[u][4] += wv[u] * p1.x; acc[u][5] += wv[u] * p1.y;
                acc[u][6] += wv[u] * p1.z; acc[u][7] += wv[u] * p1.w;
            }
        }
        // ---- + Pc + tokens, LN1, write t ----
        float4 pc0 = *(const float4*)&g_Pc[br][c0];
        float4 pc1 = *(const float4*)&g_Pc[br][c0 + 4];
        float pcv[8] = {pc0.x, pc0.y, pc0.z, pc0.w, pc1.x, pc1.y, pc1.z, pc1.w};
        #pragma unroll
        for (int u = 0; u < 6; u++) {
            int rr = r0 + u;
            int ii = rr % 24;
            float zr = zsm[rr];
            float y[8], s1 = 0.f, s2 = 0.f;
            #pragma unroll
            for (int v = 0; v < 8; v++) {
                float t = acc[u][v] + pcv[v] + zr * fesm[ii * TSTR + c0 + v];
                y[v] = t; s1 += t; s2 += t * t;
            }
            #pragma unroll
            for (int m = 8; m > 0; m >>= 1) {
                s1 += __shfl_xor_sync(0xffffffffu, s1, m);
                s2 += __shfl_xor_sync(0xffffffffu, s2, m);
            }
            float mean = s1 * (1.f / 128.f);
            float var = s2 * (1.f / 128.f) - mean * mean;
            float rstd = rsqrtf(var + 1e-5f);
            #pragma unroll
            for (int v = 0; v < 8; v++)
                tsm[rr * TSTR + c0 + v] = (y[v] - mean) * rstd * c1g[c0 + v] + c1b[c0 + v];
        }
        __syncthreads();   // t complete; Psm/Wsm dead -> reuse X for FFN staging

        // ---- FFN: 8 chunks of 64 ffn-dims ----
        float facc[6][8];
        #pragma unroll
        for (int u = 0; u < 6; u++)
            #pragma unroll
            for (int v = 0; v < 8; v++) facc[u][v] = 0.f;
        int fc0 = tx * 4;
        for (int ch = 0; ch < 8; ch++) {
            int f0 = ch * 64;
            for (int idx = tid; idx < 64 * 128; idx += 256) {
                int f = idx >> 7, c = idx & 127;
                W1T[c * W1STR + f] = w1[(f0 + f) * Dx + c];
            }
            for (int idx = tid; idx < 64 * 128; idx += 256) {
                int c = idx >> 6, f = idx & 63;
                W2s[f * W2STR + c] = w2[c * FFx + f0 + f];
            }
            if (tid < 64) b1c[tid] = b1[f0 + tid];
            __syncthreads();
            // GEMM1: h[96][64] = t[96][128] @ W1chunk^T, +b1, relu
            float hacc[6][4];
            #pragma unroll
            for (int u = 0; u < 6; u++)
                #pragma unroll
                for (int v = 0; v < 4; v++) hacc[u][v] = b1c[fc0 + v];
            for (int c = 0; c < 128; c++) {
                float tv[6];
                #pragma unroll
                for (int u = 0; u < 6; u++) tv[u] = tsm[(r0 + u) * TSTR + c];
                float4 wv = *(const float4*)&W1T[c * W1STR + fc0];
                #pragma unroll
                for (int u = 0; u < 6; u++) {
                    hacc[u][0] += tv[u] * wv.x; hacc[u][1] += tv[u] * wv.y;
                    hacc[u][2] += tv[u] * wv.z; hacc[u][3] += tv[u] * wv.w;
                }
            }
            #pragma unroll
            for (int u = 0; u < 6; u++)
                #pragma unroll
                for (int v = 0; v < 4; v++)
                    hs[(r0 + u) * HSTR + fc0 + v] = fmaxf(hacc[u][v], 0.f);
            __syncthreads();
            // GEMM2: facc[96][128] += h[96][64] @ W2chunk^T
            for (int f = 0; f < 64; f++) {
                float hv[6];
                #pragma unroll
                for (int u = 0; u < 6; u++) hv[u] = hs[(r0 + u) * HSTR + f];
                float4 wa = *(const float4*)&W2s[f * W2STR + c0];
                float4 wb = *(const float4*)&W2s[f * W2STR + c0 + 4];
                #pragma unroll
                for (int u = 0; u < 6; u++) {
                    facc[u][0] += hv[u] * wa.x; facc[u][1] += hv[u] * wa.y;
                    facc[u][2] += hv[u] * wa.z; facc[u][3] += hv[u] * wa.w;
                    facc[u][4] += hv[u] * wb.x; facc[u][5] += hv[u] * wb.y;
                    facc[u][6] += hv[u] * wb.z; facc[u][7] += hv[u] * wb.w;
                }
            }
            __syncthreads();   // before next chunk overwrites staging
        }
        // ---- epilogue: y = t + ffn + b2; fused LN2 + head via 3 reductions ----
        float4 gwa = *(const float4*)&g_gw[br][c0];
        float4 gwb = *(const float4*)&g_gw[br][c0 + 4];
        float gwv[8] = {gwa.x, gwa.y, gwa.z, gwa.w, gwb.x, gwb.y, gwb.z, gwb.w};
        float sgw = g_sc[br][0], cst = g_sc[br][1];
        #pragma unroll
        for (int u = 0; u < 6; u++) {
            int rr = r0 + u;
            float s1 = 0.f, s2 = 0.f, s3 = 0.f;
            #pragma unroll
            for (int v = 0; v < 8; v++) {
                float yv = tsm[rr * TSTR + c0 + v] + facc[u][v] + cb2[c0 + v];
                s1 += yv; s2 += yv * yv; s3 += yv * gwv[v];
            }
            #pragma unroll
            for (int m = 8; m > 0; m >>= 1) {
                s1 += __shfl_xor_sync(0xffffffffu, s1, m);
                s2 += __shfl_xor_sync(0xffffffffu, s2, m);
                s3 += __shfl_xor_sync(0xffffffffu, s3, m);
            }
            if (tx == 0) {
                float mean = s1 * (1.f / 128.f);
                float var = s2 * (1.f / 128.f) - mean * mean;
                float rstd = rsqrtf(var + 1e-5f);
                outsm[rr] += (s3 - mean * sgw) * rstd + cst;
            }
        }
        __syncthreads();   // before next branch reuses tsm / X
    }
    if (tid < 96) out[blk * 96 + tid] = outsm[tid];
}

// ---------------------------------------------------------------------------
// Launch
// ---------------------------------------------------------------------------
extern "C" void kernel_launch(void* const* d_in, const int* in_sizes, int n_in,
                              void* d_out, int out_size) {
    const float* z    = (const float*)d_in[0];
    const float* fe   = (const float*)d_in[1];
    const float* inwp = (const float*)d_in[2];
    const float* inbp = (const float*)d_in[3];
    const float* outwp= (const float*)d_in[4];
    const float* outbp= (const float*)d_in[5];
    const float* inwf = (const float*)d_in[6];
    const float* inbf = (const float*)d_in[7];
    const float* outwf= (const float*)d_in[8];
    const float* outbf= (const float*)d_in[9];
    const float* ln1g = (const float*)d_in[10];
    const float* ln1b = (const float*)d_in[11];
    const float* w1   = (const float*)d_in[12];
    const float* b1   = (const float*)d_in[13];
    const float* w2   = (const float*)d_in[14];
    const float* b2   = (const float*)d_in[15];
    const float* ln2g = (const float*)d_in[16];
    const float* ln2b = (const float*)d_in[17];
    const float* oppw = (const float*)d_in[18];
    const float* oppb = (const float*)d_in[19];
    const float* opfw = (const float*)d_in[20];
    const float* opfb = (const float*)d_in[21];
    const float* alog = (const float*)d_in[22];
    const float* bp   = (const float*)d_in[23];
    const float* bf   = (const float*)d_in[24];

    int B = in_sizes[0] / Hx;
    size_t smem = SMEM_FLOATS * sizeof(float);
    cudaFuncSetAttribute(fused_main, cudaFuncAttributeMaxDynamicSharedMemorySize, (int)smem);

    pre_qkv<<<6, 256>>>(fe, inwp, inwf);
    pre_misc<<<2, 256>>>(inbp, inbf, outwp, outbp, outwf, outbf,
                         ln2g, ln2b, oppw, oppb, opfw, opfb, alog, bp, bf);
    fused_main<<<B / 4, 256, smem>>>(z, fe, ln1g, ln1b, w1, b1, w2, b2, (float*)d_out);
}